// round 16
// baseline (speedup 1.0000x reference)
#include <cuda_runtime.h>
#include <cuda_fp16.h>
#include <math.h>

#define NPTS   73728            // 8*96*96
#define NCODE  4096
#define YELEMS 294912           // 8*4*96*96
#define LOSS_OFF YELEMS
#define IDX_OFF  (YELEMS + 1)

#define SCALE_A 256.0f          // 2^8  (exact)
#define SCALE_B 16777216.0f     // 2^24 (exact)
#define DESCALE (-4.656612873077393e-10f)  // -2^-31, exact

typedef unsigned int u32;

// ---------------- device scratch (no allocations allowed) ----------------
__device__ float  g_zz16[NPTS * 16];    // folded 16-dim point vectors [p][16]
__device__ float  g_S[NPTS];            // per-point |zf|^2 (32-dim, ref order)
__device__ uint4  g_wp16[NCODE * 5];    // per code: [8 hi fp16x2 | 8 lo fp16x2 | Wsq | pad3]
__device__ double g_part[576 * 5];      // loss partial sums per argmin CTA
__device__ float  g_colf[16 * 32];      // per-fold-block |w| column partial sums
__device__ int    g_done;               // argmin CTA completion counter

// m16n8k16 fp16 MMA, fp32 accumulate (legacy tensor path, valid on sm_100)
__device__ __forceinline__ void mma16(float c[4], u32 a0, u32 a1, u32 a2, u32 a3,
                                      u32 b0, u32 b1) {
    asm volatile(
        "mma.sync.aligned.m16n8k16.row.col.f32.f16.f16.f32 "
        "{%0,%1,%2,%3}, {%4,%5,%6,%7}, {%8,%9}, {%0,%1,%2,%3};"
        : "+f"(c[0]), "+f"(c[1]), "+f"(c[2]), "+f"(c[3])
        : "r"(a0), "r"(a1), "r"(a2), "r"(a3), "r"(b0), "r"(b1));
}

__device__ __forceinline__ u32 pack2(__half x, __half y) {
    __half2 h = __halves2half2(x, y);
    return *(u32*)&h;
}

__device__ __forceinline__ void cpasync16(u32 saddr, const void* gptr) {
    asm volatile("cp.async.cg.shared.global [%0], [%1], 16;"
                 :: "r"(saddr), "l"(gptr));
}
#define CP_COMMIT() asm volatile("cp.async.commit_group;" ::: "memory")
#define CP_WAIT(n)  asm volatile("cp.async.wait_group %0;" :: "n"(n) : "memory")

__device__ __forceinline__ double shfl_down_d(double v, int off) {
    return __shfl_down_sync(0xffffffffu, v, off);
}

// =====================================================================
// K1 (merged): blocks 0..287 = prep (trilinear+fold+S);
//              blocks 288..303 = codebook fold -> fp16 limbs + Wsq
//                                + fp32 |w| column partial sums + g_done reset.
// =====================================================================
__global__ __launch_bounds__(256) void k_prepfold(const float* __restrict__ z,
                                                  const float* __restrict__ w) {
    int b = blockIdx.x;
    if (b < 288) {
        int i = b * 256 + threadIdx.x;
        int n  = i % 96;
        int m  = (i / 96) % 96;
        int bb = i / (96 * 96);

        float vals[16];
        #pragma unroll
        for (int c = 0; c < 4; c++) {
            const float* zc = z + ((bb * 4 + c) * 9216);
            float A0[3], A1[3];
            #pragma unroll
            for (int dc = 0; dc < 3; dc++) {
                int col = n - 1 + dc;
                if (col < 0 || col > 95) { A0[dc] = 0.f; A1[dc] = 0.f; continue; }
                float zm = zc[m * 96 + col];
                float a0, a1;
                if (m == 0)  a0 = zm;
                else         a0 = __fadd_rn(__fmul_rn(0.25f, zc[(m - 1) * 96 + col]),
                                            __fmul_rn(0.75f, zm));
                if (m == 95) a1 = zm;
                else         a1 = __fadd_rn(__fmul_rn(0.75f, zm),
                                            __fmul_rn(0.25f, zc[(m + 1) * 96 + col]));
                A0[dc] = a0; A1[dc] = a1;
            }
            float v00 = (n == 0)  ? A0[1] : __fadd_rn(__fmul_rn(0.25f, A0[0]), __fmul_rn(0.75f, A0[1]));
            float v01 = (n == 95) ? A0[1] : __fadd_rn(__fmul_rn(0.75f, A0[1]), __fmul_rn(0.25f, A0[2]));
            float v10 = (n == 0)  ? A1[1] : __fadd_rn(__fmul_rn(0.25f, A1[0]), __fmul_rn(0.75f, A1[1]));
            float v11 = (n == 95) ? A1[1] : __fadd_rn(__fmul_rn(0.75f, A1[1]), __fmul_rn(0.25f, A1[2]));
            vals[c * 4 + 0] = v00; vals[c * 4 + 1] = v01;
            vals[c * 4 + 2] = v10; vals[c * 4 + 3] = v11;
        }

        float4* dst = (float4*)&g_zz16[i * 16];
        dst[0] = make_float4(vals[0],  vals[1],  vals[2],  vals[3]);
        dst[1] = make_float4(vals[4],  vals[5],  vals[6],  vals[7]);
        dst[2] = make_float4(vals[8],  vals[9],  vals[10], vals[11]);
        dst[3] = make_float4(vals[12], vals[13], vals[14], vals[15]);

        float S = 0.f;
        #pragma unroll
        for (int c = 0; c < 4; c++) {
            float sq[4];
            #pragma unroll
            for (int q = 0; q < 4; q++) sq[q] = __fmul_rn(vals[c * 4 + q], vals[c * 4 + q]);
            #pragma unroll
            for (int rep = 0; rep < 2; rep++) {
                S = __fadd_rn(S, sq[0]); S = __fadd_rn(S, sq[1]);
                S = __fadd_rn(S, sq[2]); S = __fadd_rn(S, sq[3]);
            }
        }
        g_S[i] = S;
    } else {
        __shared__ float cp8[8][32];
        if (threadIdx.x == 0 && b == 303) g_done = 0;   // reset completion counter

        int fb = b - 288;
        int j = fb * 256 + threadIdx.x;
        float wv[32];
        const float4* src = (const float4*)(w + j * 32);
        #pragma unroll
        for (int q = 0; q < 8; q++) {
            float4 v = src[q];
            wv[q * 4 + 0] = v.x; wv[q * 4 + 1] = v.y; wv[q * 4 + 2] = v.z; wv[q * 4 + 3] = v.w;
        }
        float wf[16];
        #pragma unroll
        for (int k = 0; k < 16; k++) {
            int e0 = ((k >> 2) << 3) + (k & 3);
            wf[k] = __fmul_rn(__fadd_rn(wv[e0], wv[e0 + 4]), SCALE_B);  // pow2, exact
        }
        u32 row[20];
        #pragma unroll
        for (int s = 0; s < 8; s++) {
            float x = wf[2 * s], y = wf[2 * s + 1];
            __half hx = __float2half_rn(x), hy = __float2half_rn(y);
            __half lx = __float2half_rn(__fadd_rn(x, -__half2float(hx)));
            __half ly = __float2half_rn(__fadd_rn(y, -__half2float(hy)));
            row[s]     = pack2(hx, hy);
            row[8 + s] = pack2(lx, ly);
        }
        float W = 0.f;
        #pragma unroll
        for (int e = 0; e < 32; e++) W = __fadd_rn(W, __fmul_rn(wv[e], wv[e]));
        row[16] = __float_as_uint(W);
        row[17] = 0u; row[18] = 0u; row[19] = 0u;

        uint4* dst = &g_wp16[j * 5];
        dst[0] = make_uint4(row[0],  row[1],  row[2],  row[3]);
        dst[1] = make_uint4(row[4],  row[5],  row[6],  row[7]);
        dst[2] = make_uint4(row[8],  row[9],  row[10], row[11]);
        dst[3] = make_uint4(row[12], row[13], row[14], row[15]);
        dst[4] = make_uint4(row[16], row[17], row[18], row[19]);

        // |w| column partial sums (fp32) across this block's 256 rows
        int lane = threadIdx.x & 31, warp = threadIdx.x >> 5;
        #pragma unroll
        for (int e = 0; e < 32; e++) {
            float v = fabsf(wv[e]);
            #pragma unroll
            for (int off = 16; off > 0; off >>= 1)
                v += __shfl_down_sync(0xffffffffu, v, off);
            if (lane == 0) cp8[warp][e] = v;
        }
        __syncthreads();
        if (threadIdx.x < 32) {
            float tot = 0.f;
            #pragma unroll
            for (int ww = 0; ww < 8; ww++) tot += cp8[ww][threadIdx.x];
            g_colf[fb * 32 + threadIdx.x] = tot;
        }
    }
}

// =====================================================================
// K2: fp16 2-limb 3-product mma.sync GEMM + fused argmin
//     + fused gather tail (y/idx/loss partials for this CTA's points)
//     + last-finishing CTA assembles the loss scalar.
// =====================================================================
__global__ __launch_bounds__(256, 2) void k_argmin_mma(const float* __restrict__ w,
                                                       float* __restrict__ out,
                                                       int out_size) {
    __shared__ u32    Bp[2][256 * 20];   // double buffer, stride-20 rows
    __shared__ int    ibuf[128];
    __shared__ double rbuf[4][5];
    __shared__ double ls[5];
    __shared__ int    isLast;

    int tid  = threadIdx.x;
    int wid  = tid >> 5;
    int lane = tid & 31;
    int g = lane >> 2, t = lane & 3;
    int pbase = blockIdx.x * 128;
    int p0 = pbase + wid * 16 + g;
    int p1 = p0 + 8;

    // ---- A fragments: fp16 hi/lo, scaled by 2^8 (exact) ----
    u32 ah[4], al[4];
    {
        const float* z0 = &g_zz16[p0 * 16];
        const float* z1 = &g_zz16[p1 * 16];
        float a[4][2];
        a[0][0] = z0[2 * t] * SCALE_A;     a[0][1] = z0[2 * t + 1] * SCALE_A;
        a[1][0] = z1[2 * t] * SCALE_A;     a[1][1] = z1[2 * t + 1] * SCALE_A;
        a[2][0] = z0[2 * t + 8] * SCALE_A; a[2][1] = z0[2 * t + 9] * SCALE_A;
        a[3][0] = z1[2 * t + 8] * SCALE_A; a[3][1] = z1[2 * t + 9] * SCALE_A;
        #pragma unroll
        for (int q = 0; q < 4; q++) {
            __half hx = __float2half_rn(a[q][0]), hy = __float2half_rn(a[q][1]);
            __half lx = __float2half_rn(__fadd_rn(a[q][0], -__half2float(hx)));
            __half ly = __float2half_rn(__fadd_rn(a[q][1], -__half2float(hy)));
            ah[q] = pack2(hx, hy);
            al[q] = pack2(lx, ly);
        }
    }
    float S0 = g_S[p0], S1 = g_S[p1];

    float bd0 = __int_as_float(0x7f800000), bd1 = bd0;
    int   bj0 = 0, bj1 = 0;

    u32 sbase0 = (u32)__cvta_generic_to_shared(&Bp[0][0]);
    u32 sbase1 = (u32)__cvta_generic_to_shared(&Bp[1][0]);

    // prologue: async-load chunk 0 into buffer 0
    {
        const uint4* gsrc = &g_wp16[0];
        #pragma unroll
        for (int it = 0; it < 5; it++)
            cpasync16(sbase0 + (it * 256 + tid) * 16, gsrc + it * 256 + tid);
        CP_COMMIT();
    }

    for (int nb = 0; nb < 16; nb++) {
        int cur = nb & 1;
        if (nb + 1 < 16) {
            u32 sb = (cur ? sbase0 : sbase1);
            const uint4* gsrc = &g_wp16[(nb + 1) * 256 * 5];
            #pragma unroll
            for (int it = 0; it < 5; it++)
                cpasync16(sb + (it * 256 + tid) * 16, gsrc + it * 256 + tid);
            CP_COMMIT();
            CP_WAIT(1);
        } else {
            CP_WAIT(0);
        }
        __syncthreads();

        const u32* Bc = &Bp[cur][0];
        int nbase = nb * 256;

        #pragma unroll 4
        for (int nt = 0; nt < 32; nt++) {
            const u32* br = &Bc[(nt * 8 + g) * 20];
            u32 bh0 = br[t];
            u32 bh1 = br[t + 4];
            u32 bl0 = br[t + 8];
            u32 bl1 = br[t + 12];

            float c[4] = {0.f, 0.f, 0.f, 0.f};
            mma16(c, ah[0], ah[1], ah[2], ah[3], bh0, bh1);
            mma16(c, al[0], al[1], al[2], al[3], bh0, bh1);
            mma16(c, ah[0], ah[1], ah[2], ah[3], bl0, bl1);

            int nc0 = nt * 8 + 2 * t;
            float w0 = __uint_as_float(Bc[nc0 * 20 + 16]);
            float w1 = __uint_as_float(Bc[(nc0 + 1) * 20 + 16]);
            int j0 = nbase + nc0, j1 = j0 + 1;
            float d00 = __fmaf_rn(DESCALE, c[0], __fadd_rn(S0, w0));
            float d01 = __fmaf_rn(DESCALE, c[1], __fadd_rn(S0, w1));
            float d10 = __fmaf_rn(DESCALE, c[2], __fadd_rn(S1, w0));
            float d11 = __fmaf_rn(DESCALE, c[3], __fadd_rn(S1, w1));
            if (d00 < bd0) { bd0 = d00; bj0 = j0; }
            if (d01 < bd0) { bd0 = d01; bj0 = j1; }
            if (d10 < bd1) { bd1 = d10; bj1 = j0; }
            if (d11 < bd1) { bd1 = d11; bj1 = j1; }
        }
        __syncthreads();   // buffer cur may be overwritten next iteration
    }

    // lexicographic (d, j) reduce across the 4 lanes sharing each row
    #pragma unroll
    for (int off = 2; off > 0; off >>= 1) {
        float od = __shfl_down_sync(0xffffffffu, bd0, off, 4);
        int   oj = __shfl_down_sync(0xffffffffu, bj0, off, 4);
        if (od < bd0 || (od == bd0 && oj < bj0)) { bd0 = od; bj0 = oj; }
        od = __shfl_down_sync(0xffffffffu, bd1, off, 4);
        oj = __shfl_down_sync(0xffffffffu, bj1, off, 4);
        if (od < bd1 || (od == bd1 && oj < bj1)) { bd1 = od; bj1 = oj; }
    }
    if (t == 0) {
        ibuf[wid * 16 + g] = bj0;
        ibuf[wid * 16 + g + 8] = bj1;
    }
    __syncthreads();

    // ---------- fused gather tail (threads 0..127, one point each) ----------
    if (tid < 128) {
        int i = pbase + tid;
        int idx = ibuf[tid];

        float cw[32];
        const float4* src = (const float4*)(w + idx * 32);
        #pragma unroll
        for (int q = 0; q < 8; q++) {
            float4 v = src[q];
            cw[q * 4 + 0] = v.x; cw[q * 4 + 1] = v.y; cw[q * 4 + 2] = v.z; cw[q * 4 + 3] = v.w;
        }
        float vv[16];
        const float4* vsrc = (const float4*)&g_zz16[i * 16];
        #pragma unroll
        for (int q = 0; q < 4; q++) {
            float4 v = vsrc[q];
            vv[q * 4 + 0] = v.x; vv[q * 4 + 1] = v.y; vv[q * 4 + 2] = v.z; vv[q * 4 + 3] = v.w;
        }

        int n = i % 96, m = (i / 96) % 96, bb = i / 9216;
        #pragma unroll
        for (int c = 0; c < 4; c++) {
            double s = 0.0;
            #pragma unroll
            for (int q = 0; q < 8; q++) s += (double)cw[c * 8 + q];
            int yoff = ((bb * 4 + c) * 9216) + m * 96 + n;
            if (yoff < out_size) out[yoff] = (float)(s * 0.125);
        }
        if (IDX_OFF + i < out_size) out[IDX_OFF + i] = (float)idx;

        double sq = 0, sz = 0, sq2 = 0, sz2 = 0, sx = 0;
        #pragma unroll
        for (int e = 0; e < 32; e++) {
            double q = (double)cw[e];
            double zv = (double)vv[(e >> 3) * 4 + (e & 3)];
            sq += q; sz += zv; sq2 += q * q; sz2 += zv * zv; sx += q * zv;
        }
        double vals5[5] = {sq, sz, sq2, sz2, sx};
        int warp = tid >> 5;   // 0..3
        #pragma unroll
        for (int s = 0; s < 5; s++) {
            double v = vals5[s];
            #pragma unroll
            for (int off = 16; off > 0; off >>= 1)
                v += __shfl_down_sync(0xffffffffu, v, off);
            if (lane == 0) rbuf[warp][s] = v;
        }
    }
    __syncthreads();
    if (wid == 0 && tid < 32) {
        #pragma unroll
        for (int s = 0; s < 5; s++) {
            double v = (lane < 4) ? rbuf[lane][s] : 0.0;
            #pragma unroll
            for (int off = 2; off > 0; off >>= 1)
                v += shfl_down_d(v, off);
            if (lane == 0) g_part[blockIdx.x * 5 + s] = v;
        }
    }
    __syncthreads();

    // ---- completion count; last CTA assembles the loss ----
    if (tid == 0) {
        __threadfence();
        int old = atomicAdd(&g_done, 1);
        isLast = (old == 575);
    }
    __syncthreads();
    if (!isLast) return;
    __threadfence();

    // ls reduce (warps 0..4 over 576 CTA partials)
    if (wid < 5) {
        double acc = 0.0;
        for (int b = lane; b < 576; b += 32) acc += g_part[b * 5 + wid];
        #pragma unroll
        for (int off = 16; off > 0; off >>= 1) acc += shfl_down_d(acc, off);
        if (lane == 0) ls[wid] = acc;
    }
    __syncthreads();

    if (tid < 32) {
        // column totals over 16 fold-block partials, then max
        float tot = 0.f;
        #pragma unroll
        for (int fb = 0; fb < 16; fb++) tot += g_colf[fb * 32 + tid];
        float v = tot;
        #pragma unroll
        for (int off = 16; off > 0; off >>= 1) {
            float o = __shfl_down_sync(0xffffffffu, v, off);
            if (o > v) v = o;
        }
        if (tid == 0) {
            double colmax = (double)v;
            double nel = (double)NPTS * 32.0;
            double Sq = ls[0], Sz = ls[1], Sq2 = ls[2], Sz2 = ls[3], Sx = ls[4];
            double mse = (Sq2 - 2.0 * Sx + Sz2) / nel;
            double mq = Sq / nel, mz = Sz / nel;
            double cov = Sx - nel * mq * mz;
            double vq = Sq2 - nel * mq * mq;
            double vz = Sz2 - nel * mz * mz;
            double cost = cov / (sqrt(vq) * sqrt(vz));
            double loss = 1.25 * mse + (0.5 + 0.5 * cost) + 0.01 * colmax;
            if (LOSS_OFF < out_size) out[LOSS_OFF] = (float)loss;
        }
    }
}

// =====================================================================
extern "C" void kernel_launch(void* const* d_in, const int* in_sizes, int n_in,
                              void* d_out, int out_size) {
    const float* z = (const float*)d_in[0];
    const float* w = (const float*)d_in[1];
    if (n_in >= 2 && in_sizes[0] == NCODE * 32 && in_sizes[1] == YELEMS) {
        const float* tmp = z; z = w; w = tmp;   // defensive input-order guard
    }
    float* out = (float*)d_out;

    k_prepfold  <<<304, 256>>>(z, w);
    k_argmin_mma<<<576, 256>>>(w, out, out_size);
}

// round 17
// speedup vs baseline: 1.0608x; 1.0608x over previous
#include <cuda_runtime.h>
#include <cuda_fp16.h>
#include <math.h>

#define NPTS   73728            // 8*96*96
#define NCODE  4096
#define YELEMS 294912           // 8*4*96*96
#define LOSS_OFF YELEMS
#define IDX_OFF  (YELEMS + 1)

#define SCALE_A 256.0f          // 2^8  (exact)
#define SCALE_B 16777216.0f     // 2^24 (exact)
#define DESCALE (-4.656612873077393e-10f)  // -2^-31, exact

typedef unsigned int u32;

// ---------------- device scratch (no allocations allowed) ----------------
__device__ float  g_zz16[NPTS * 16];    // folded 16-dim point vectors [p][16]
__device__ float  g_S[NPTS];            // per-point |zf|^2 (32-dim, ref order)
__device__ uint4  g_wp16[NCODE * 5];    // per code: [8 hi fp16x2 | 8 lo fp16x2 | Wsq | pad3]
__device__ int    g_idx[NPTS];
__device__ double g_part[288 * 5];      // loss partial sums per gather block
__device__ float  g_colf[16 * 32];      // per-fold-block |w| column partial sums
__device__ int    g_done;               // gather completion counter

// m16n8k16 fp16 MMA, fp32 accumulate (legacy tensor path, valid on sm_100)
__device__ __forceinline__ void mma16(float c[4], u32 a0, u32 a1, u32 a2, u32 a3,
                                      u32 b0, u32 b1) {
    asm volatile(
        "mma.sync.aligned.m16n8k16.row.col.f32.f16.f16.f32 "
        "{%0,%1,%2,%3}, {%4,%5,%6,%7}, {%8,%9}, {%0,%1,%2,%3};"
        : "+f"(c[0]), "+f"(c[1]), "+f"(c[2]), "+f"(c[3])
        : "r"(a0), "r"(a1), "r"(a2), "r"(a3), "r"(b0), "r"(b1));
}

__device__ __forceinline__ u32 pack2(__half x, __half y) {
    __half2 h = __halves2half2(x, y);
    return *(u32*)&h;
}

__device__ __forceinline__ void cpasync16(u32 saddr, const void* gptr) {
    asm volatile("cp.async.cg.shared.global [%0], [%1], 16;"
                 :: "r"(saddr), "l"(gptr));
}
#define CP_COMMIT() asm volatile("cp.async.commit_group;" ::: "memory")
#define CP_WAIT(n)  asm volatile("cp.async.wait_group %0;" :: "n"(n) : "memory")

__device__ __forceinline__ double shfl_down_d(double v, int off) {
    return __shfl_down_sync(0xffffffffu, v, off);
}

// =====================================================================
// K1 (merged): blocks 0..287 = prep (trilinear+fold+S);
//              blocks 288..303 = codebook fold -> fp16 limbs + Wsq
//                                + fp32 |w| column partial sums + g_done reset.
// =====================================================================
__global__ __launch_bounds__(256) void k_prepfold(const float* __restrict__ z,
                                                  const float* __restrict__ w) {
    int b = blockIdx.x;
    if (b < 288) {
        int i = b * 256 + threadIdx.x;
        int n  = i % 96;
        int m  = (i / 96) % 96;
        int bb = i / (96 * 96);

        float vals[16];
        #pragma unroll
        for (int c = 0; c < 4; c++) {
            const float* zc = z + ((bb * 4 + c) * 9216);
            float A0[3], A1[3];
            #pragma unroll
            for (int dc = 0; dc < 3; dc++) {
                int col = n - 1 + dc;
                if (col < 0 || col > 95) { A0[dc] = 0.f; A1[dc] = 0.f; continue; }
                float zm = zc[m * 96 + col];
                float a0, a1;
                if (m == 0)  a0 = zm;
                else         a0 = __fadd_rn(__fmul_rn(0.25f, zc[(m - 1) * 96 + col]),
                                            __fmul_rn(0.75f, zm));
                if (m == 95) a1 = zm;
                else         a1 = __fadd_rn(__fmul_rn(0.75f, zm),
                                            __fmul_rn(0.25f, zc[(m + 1) * 96 + col]));
                A0[dc] = a0; A1[dc] = a1;
            }
            float v00 = (n == 0)  ? A0[1] : __fadd_rn(__fmul_rn(0.25f, A0[0]), __fmul_rn(0.75f, A0[1]));
            float v01 = (n == 95) ? A0[1] : __fadd_rn(__fmul_rn(0.75f, A0[1]), __fmul_rn(0.25f, A0[2]));
            float v10 = (n == 0)  ? A1[1] : __fadd_rn(__fmul_rn(0.25f, A1[0]), __fmul_rn(0.75f, A1[1]));
            float v11 = (n == 95) ? A1[1] : __fadd_rn(__fmul_rn(0.75f, A1[1]), __fmul_rn(0.25f, A1[2]));
            vals[c * 4 + 0] = v00; vals[c * 4 + 1] = v01;
            vals[c * 4 + 2] = v10; vals[c * 4 + 3] = v11;
        }

        float4* dst = (float4*)&g_zz16[i * 16];
        dst[0] = make_float4(vals[0],  vals[1],  vals[2],  vals[3]);
        dst[1] = make_float4(vals[4],  vals[5],  vals[6],  vals[7]);
        dst[2] = make_float4(vals[8],  vals[9],  vals[10], vals[11]);
        dst[3] = make_float4(vals[12], vals[13], vals[14], vals[15]);

        float S = 0.f;
        #pragma unroll
        for (int c = 0; c < 4; c++) {
            float sq[4];
            #pragma unroll
            for (int q = 0; q < 4; q++) sq[q] = __fmul_rn(vals[c * 4 + q], vals[c * 4 + q]);
            #pragma unroll
            for (int rep = 0; rep < 2; rep++) {
                S = __fadd_rn(S, sq[0]); S = __fadd_rn(S, sq[1]);
                S = __fadd_rn(S, sq[2]); S = __fadd_rn(S, sq[3]);
            }
        }
        g_S[i] = S;
    } else {
        __shared__ float cp8[8][32];
        if (threadIdx.x == 0 && b == 303) g_done = 0;   // reset gather counter

        int fb = b - 288;
        int j = fb * 256 + threadIdx.x;
        float wv[32];
        const float4* src = (const float4*)(w + j * 32);
        #pragma unroll
        for (int q = 0; q < 8; q++) {
            float4 v = src[q];
            wv[q * 4 + 0] = v.x; wv[q * 4 + 1] = v.y; wv[q * 4 + 2] = v.z; wv[q * 4 + 3] = v.w;
        }
        float wf[16];
        #pragma unroll
        for (int k = 0; k < 16; k++) {
            int e0 = ((k >> 2) << 3) + (k & 3);
            wf[k] = __fmul_rn(__fadd_rn(wv[e0], wv[e0 + 4]), SCALE_B);  // pow2, exact
        }
        u32 row[20];
        #pragma unroll
        for (int s = 0; s < 8; s++) {
            float x = wf[2 * s], y = wf[2 * s + 1];
            __half hx = __float2half_rn(x), hy = __float2half_rn(y);
            __half lx = __float2half_rn(__fadd_rn(x, -__half2float(hx)));
            __half ly = __float2half_rn(__fadd_rn(y, -__half2float(hy)));
            row[s]     = pack2(hx, hy);
            row[8 + s] = pack2(lx, ly);
        }
        float W = 0.f;
        #pragma unroll
        for (int e = 0; e < 32; e++) W = __fadd_rn(W, __fmul_rn(wv[e], wv[e]));
        row[16] = __float_as_uint(W);
        row[17] = 0u; row[18] = 0u; row[19] = 0u;

        uint4* dst = &g_wp16[j * 5];
        dst[0] = make_uint4(row[0],  row[1],  row[2],  row[3]);
        dst[1] = make_uint4(row[4],  row[5],  row[6],  row[7]);
        dst[2] = make_uint4(row[8],  row[9],  row[10], row[11]);
        dst[3] = make_uint4(row[12], row[13], row[14], row[15]);
        dst[4] = make_uint4(row[16], row[17], row[18], row[19]);

        // |w| column partial sums (fp32) across this block's 256 rows
        int lane = threadIdx.x & 31, warp = threadIdx.x >> 5;
        #pragma unroll
        for (int e = 0; e < 32; e++) {
            float v = fabsf(wv[e]);
            #pragma unroll
            for (int off = 16; off > 0; off >>= 1)
                v += __shfl_down_sync(0xffffffffu, v, off);
            if (lane == 0) cp8[warp][e] = v;
        }
        __syncthreads();
        if (threadIdx.x < 32) {
            float tot = 0.f;
            #pragma unroll
            for (int ww = 0; ww < 8; ww++) tot += cp8[ww][threadIdx.x];
            g_colf[fb * 32 + threadIdx.x] = tot;
        }
    }
}

// =====================================================================
// K2: fp16 2-limb 3-product mma.sync GEMM + fused argmin,
//     double-buffered B staging via cp.async; 3 CTAs/SM for latency hiding.
// =====================================================================
__global__ __launch_bounds__(256, 3) void k_argmin_mma() {
    __shared__ u32 Bp[2][256 * 20];   // double buffer, stride-20 rows

    int tid  = threadIdx.x;
    int wid  = tid >> 5;
    int lane = tid & 31;
    int g = lane >> 2, t = lane & 3;
    int pbase = blockIdx.x * 128;
    int p0 = pbase + wid * 16 + g;
    int p1 = p0 + 8;

    // ---- A fragments: fp16 hi/lo, scaled by 2^8 (exact) ----
    u32 ah[4], al[4];
    {
        const float* z0 = &g_zz16[p0 * 16];
        const float* z1 = &g_zz16[p1 * 16];
        float a[4][2];
        a[0][0] = z0[2 * t] * SCALE_A;     a[0][1] = z0[2 * t + 1] * SCALE_A;
        a[1][0] = z1[2 * t] * SCALE_A;     a[1][1] = z1[2 * t + 1] * SCALE_A;
        a[2][0] = z0[2 * t + 8] * SCALE_A; a[2][1] = z0[2 * t + 9] * SCALE_A;
        a[3][0] = z1[2 * t + 8] * SCALE_A; a[3][1] = z1[2 * t + 9] * SCALE_A;
        #pragma unroll
        for (int q = 0; q < 4; q++) {
            __half hx = __float2half_rn(a[q][0]), hy = __float2half_rn(a[q][1]);
            __half lx = __float2half_rn(__fadd_rn(a[q][0], -__half2float(hx)));
            __half ly = __float2half_rn(__fadd_rn(a[q][1], -__half2float(hy)));
            ah[q] = pack2(hx, hy);
            al[q] = pack2(lx, ly);
        }
    }
    float S0 = g_S[p0], S1 = g_S[p1];

    float bd0 = __int_as_float(0x7f800000), bd1 = bd0;
    int   bj0 = 0, bj1 = 0;

    u32 sbase0 = (u32)__cvta_generic_to_shared(&Bp[0][0]);
    u32 sbase1 = (u32)__cvta_generic_to_shared(&Bp[1][0]);

    // prologue: async-load chunk 0 into buffer 0
    {
        const uint4* gsrc = &g_wp16[0];
        #pragma unroll
        for (int it = 0; it < 5; it++)
            cpasync16(sbase0 + (it * 256 + tid) * 16, gsrc + it * 256 + tid);
        CP_COMMIT();
    }

    for (int nb = 0; nb < 16; nb++) {
        int cur = nb & 1;
        if (nb + 1 < 16) {
            u32 sb = (cur ? sbase0 : sbase1);
            const uint4* gsrc = &g_wp16[(nb + 1) * 256 * 5];
            #pragma unroll
            for (int it = 0; it < 5; it++)
                cpasync16(sb + (it * 256 + tid) * 16, gsrc + it * 256 + tid);
            CP_COMMIT();
            CP_WAIT(1);
        } else {
            CP_WAIT(0);
        }
        __syncthreads();

        const u32* Bc = &Bp[cur][0];
        int nbase = nb * 256;

        #pragma unroll 4
        for (int nt = 0; nt < 32; nt++) {
            const u32* br = &Bc[(nt * 8 + g) * 20];
            u32 bh0 = br[t];
            u32 bh1 = br[t + 4];
            u32 bl0 = br[t + 8];
            u32 bl1 = br[t + 12];

            float c[4] = {0.f, 0.f, 0.f, 0.f};
            mma16(c, ah[0], ah[1], ah[2], ah[3], bh0, bh1);
            mma16(c, al[0], al[1], al[2], al[3], bh0, bh1);
            mma16(c, ah[0], ah[1], ah[2], ah[3], bl0, bl1);

            int nc0 = nt * 8 + 2 * t;
            float w0 = __uint_as_float(Bc[nc0 * 20 + 16]);
            float w1 = __uint_as_float(Bc[(nc0 + 1) * 20 + 16]);
            int j0 = nbase + nc0, j1 = j0 + 1;
            float d00 = __fmaf_rn(DESCALE, c[0], __fadd_rn(S0, w0));
            float d01 = __fmaf_rn(DESCALE, c[1], __fadd_rn(S0, w1));
            float d10 = __fmaf_rn(DESCALE, c[2], __fadd_rn(S1, w0));
            float d11 = __fmaf_rn(DESCALE, c[3], __fadd_rn(S1, w1));
            if (d00 < bd0) { bd0 = d00; bj0 = j0; }
            if (d01 < bd0) { bd0 = d01; bj0 = j1; }
            if (d10 < bd1) { bd1 = d10; bj1 = j0; }
            if (d11 < bd1) { bd1 = d11; bj1 = j1; }
        }
        __syncthreads();   // buffer cur may be overwritten next iteration
    }

    // lexicographic (d, j) reduce across the 4 lanes sharing each row
    #pragma unroll
    for (int off = 2; off > 0; off >>= 1) {
        float od = __shfl_down_sync(0xffffffffu, bd0, off, 4);
        int   oj = __shfl_down_sync(0xffffffffu, bj0, off, 4);
        if (od < bd0 || (od == bd0 && oj < bj0)) { bd0 = od; bj0 = oj; }
        od = __shfl_down_sync(0xffffffffu, bd1, off, 4);
        oj = __shfl_down_sync(0xffffffffu, bj1, off, 4);
        if (od < bd1 || (od == bd1 && oj < bj1)) { bd1 = od; bj1 = oj; }
    }
    if (t == 0) {
        g_idx[p0] = bj0;
        g_idx[p1] = bj1;
    }
}

// =====================================================================
// K3: gather codewords -> y, idx output, loss partial sums.
//     The LAST finishing block also assembles the loss scalar.
// =====================================================================
__global__ __launch_bounds__(256) void k_gather(const float* __restrict__ w,
                                                float* __restrict__ out,
                                                int out_size) {
    __shared__ double rbuf[8][5];
    __shared__ double ls[5];
    __shared__ int isLast;
    int tid = threadIdx.x;
    int i = blockIdx.x * 256 + tid;

    int idx = g_idx[i];
    float cw[32];
    const float4* src = (const float4*)(w + idx * 32);
    #pragma unroll
    for (int q = 0; q < 8; q++) {
        float4 v = src[q];
        cw[q * 4 + 0] = v.x; cw[q * 4 + 1] = v.y; cw[q * 4 + 2] = v.z; cw[q * 4 + 3] = v.w;
    }
    float vv[16];
    const float4* vsrc = (const float4*)&g_zz16[i * 16];
    #pragma unroll
    for (int q = 0; q < 4; q++) {
        float4 v = vsrc[q];
        vv[q * 4 + 0] = v.x; vv[q * 4 + 1] = v.y; vv[q * 4 + 2] = v.z; vv[q * 4 + 3] = v.w;
    }

    int n = i % 96, m = (i / 96) % 96, bb = i / 9216;
    #pragma unroll
    for (int c = 0; c < 4; c++) {
        double s = 0.0;
        #pragma unroll
        for (int q = 0; q < 8; q++) s += (double)cw[c * 8 + q];
        int yoff = ((bb * 4 + c) * 9216) + m * 96 + n;
        if (yoff < out_size) out[yoff] = (float)(s * 0.125);
    }
    if (IDX_OFF + i < out_size) out[IDX_OFF + i] = (float)idx;

    double sq = 0, sz = 0, sq2 = 0, sz2 = 0, sx = 0;
    #pragma unroll
    for (int e = 0; e < 32; e++) {
        double q = (double)cw[e];
        double zv = (double)vv[(e >> 3) * 4 + (e & 3)];
        sq += q; sz += zv; sq2 += q * q; sz2 += zv * zv; sx += q * zv;
    }
    double vals[5] = {sq, sz, sq2, sz2, sx};
    int lane = tid & 31, warp = tid >> 5;
    #pragma unroll
    for (int s = 0; s < 5; s++) {
        double v = vals[s];
        #pragma unroll
        for (int off = 16; off > 0; off >>= 1)
            v += __shfl_down_sync(0xffffffffu, v, off);
        if (lane == 0) rbuf[warp][s] = v;
    }
    __syncthreads();
    if (warp == 0) {
        #pragma unroll
        for (int s = 0; s < 5; s++) {
            double v = (lane < 8) ? rbuf[lane][s] : 0.0;
            #pragma unroll
            for (int off = 4; off > 0; off >>= 1)
                v += __shfl_down_sync(0xffffffffu, v, off);
            if (lane == 0) g_part[blockIdx.x * 5 + s] = v;
        }
    }
    __syncthreads();

    // ---- completion count; last block assembles the loss ----
    if (tid == 0) {
        __threadfence();
        int old = atomicAdd(&g_done, 1);
        isLast = (old == 287);
    }
    __syncthreads();
    if (!isLast) return;
    __threadfence();

    // ls reduce (warps 0..4 over 288 block partials)
    if (warp < 5) {
        double acc = 0.0;
        for (int b = lane; b < 288; b += 32) acc += g_part[b * 5 + warp];
        #pragma unroll
        for (int off = 16; off > 0; off >>= 1) acc += shfl_down_d(acc, off);
        if (lane == 0) ls[warp] = acc;
    }
    __syncthreads();

    if (tid < 32) {
        // column totals over 16 fold-block partials, then max
        float tot = 0.f;
        #pragma unroll
        for (int fb = 0; fb < 16; fb++) tot += g_colf[fb * 32 + tid];
        float v = tot;
        #pragma unroll
        for (int off = 16; off > 0; off >>= 1) {
            float o = __shfl_down_sync(0xffffffffu, v, off);
            if (o > v) v = o;
        }
        if (tid == 0) {
            double colmax = (double)v;
            double nel = (double)NPTS * 32.0;
            double Sq = ls[0], Sz = ls[1], Sq2 = ls[2], Sz2 = ls[3], Sx = ls[4];
            double mse = (Sq2 - 2.0 * Sx + Sz2) / nel;
            double mq = Sq / nel, mz = Sz / nel;
            double cov = Sx - nel * mq * mz;
            double vq = Sq2 - nel * mq * mq;
            double vz = Sz2 - nel * mz * mz;
            double cost = cov / (sqrt(vq) * sqrt(vz));
            double loss = 1.25 * mse + (0.5 + 0.5 * cost) + 0.01 * colmax;
            if (LOSS_OFF < out_size) out[LOSS_OFF] = (float)loss;
        }
    }
}

// =====================================================================
extern "C" void kernel_launch(void* const* d_in, const int* in_sizes, int n_in,
                              void* d_out, int out_size) {
    const float* z = (const float*)d_in[0];
    const float* w = (const float*)d_in[1];
    if (n_in >= 2 && in_sizes[0] == NCODE * 32 && in_sizes[1] == YELEMS) {
        const float* tmp = z; z = w; w = tmp;   // defensive input-order guard
    }
    float* out = (float*)d_out;

    k_prepfold  <<<304, 256>>>(z, w);
    k_argmin_mma<<<576, 256>>>();
    k_gather    <<<288, 256>>>(w, out, out_size);
}